// round 9
// baseline (speedup 1.0000x reference)
#include <cuda_runtime.h>
#include <cuda_bf16.h>
#include <cstdint>

// ---------------- problem constants ----------------
#define NMAX 50000
#define EMAX 600000
#define GMAX 256
#define DH 128

// ---------------- device scratch ----------------
__device__ float g_hA [(size_t)NMAX * DH];
__device__ float g_hB [(size_t)NMAX * DH];
__device__ int   g_deg[NMAX];
__device__ int   g_rowptr[NMAX + 1];
__device__ int   g_cursor[NMAX];
__device__ int   g_srcs[EMAX];
__device__ float g_gcnt[GMAX];
// pre-split bf16 hi/lo weight images, padded [n][2K+8] layout
__device__ unsigned short g_Bimg[167168];

// ---------------- fused setup: zero deg/out/gcnt + build 3 weight images ----
__device__ __forceinline__ void prep_B_elem(const float* Wl, const float* Wr,
                                            unsigned short* img, int chunks, int t) {
    int strideB = chunks * 128 + 8;
    int Ktot    = chunks * 64;
    int nn = t / strideB;
    int kk = t - nn * strideB;
    if (kk < Ktot) {
        int half = chunks * 32;
        const float* W; int k;
        if (kk < half) { W = Wl; k = kk; } else { W = Wr; k = kk - half; }
        float v = W[(size_t)k * 128 + nn];
        __nv_bfloat16 h = __float2bfloat16_rn(v);
        __nv_bfloat16 l = __float2bfloat16_rn(v - __bfloat162float(h));
        img[nn * strideB + kk]        = __bfloat16_as_ushort(h);
        img[nn * strideB + Ktot + kk] = __bfloat16_as_ushort(l);
    } else if (kk >= 2 * Ktot) {
        img[t] = 0;
    }
}

__global__ void setup_kernel(const float* __restrict__ Wl1, const float* __restrict__ Wr1,
                             const float* __restrict__ Wl2, const float* __restrict__ Wr2,
                             const float* __restrict__ Wl3, const float* __restrict__ Wr3,
                             unsigned short* __restrict__ img,
                             float* __restrict__ out, int n, int G) {
    const int s1 = n;
    const int s2 = s1 + G * 128;
    const int s3 = s2 + G;
    const int s4 = s3 + 128 * 264;
    const int s5 = s4 + 128 * 520;
    const int s6 = s5 + 128 * 520;
    for (int t = blockIdx.x * blockDim.x + threadIdx.x; t < s6;
         t += gridDim.x * blockDim.x) {
        if (t < s1)       g_deg[t] = 0;
        else if (t < s2)  out[t - s1] = 0.0f;
        else if (t < s3)  g_gcnt[t - s2] = 0.0f;
        else if (t < s4)  prep_B_elem(Wl1, Wr1, img,          2, t - s3);
        else if (t < s5)  prep_B_elem(Wl2, Wr2, img + 33792,  4, t - s4);
        else              prep_B_elem(Wl3, Wr3, img + 100352, 4, t - s5);
    }
}

// ---------------- CSR build ----------------
__global__ void count_deg_kernel(const int* __restrict__ dst, int E, int n) {
    int e = blockIdx.x * blockDim.x + threadIdx.x;
    if (e < E) {
        int d = dst[e];
        if (d >= 0 && d < n) atomicAdd(&g_deg[d], 1);
    }
}

__global__ void scan_kernel(int n) {
    __shared__ int sh[1024];
    int tid = threadIdx.x;
    int chunk = (n + 1023) / 1024;
    int beg = tid * chunk;
    int end = min(beg + chunk, n);
    int s = 0;
    for (int i = beg; i < end; i++) s += g_deg[i];
    sh[tid] = s;
    __syncthreads();
    for (int off = 1; off < 1024; off <<= 1) {
        int v = (tid >= off) ? sh[tid - off] : 0;
        __syncthreads();
        sh[tid] += v;
        __syncthreads();
    }
    int run = sh[tid] - s;
    for (int i = beg; i < end; i++) {
        g_rowptr[i] = run;
        g_cursor[i] = run;
        run += g_deg[i];
    }
    if (tid == 1023) g_rowptr[n] = sh[1023];
}

__global__ void scatter_kernel(const int* __restrict__ src,
                               const int* __restrict__ dst, int E, int n) {
    int e = blockIdx.x * blockDim.x + threadIdx.x;
    if (e < E) {
        int d = dst[e];
        int s = src[e];
        if (d >= 0 && d < n && s >= 0 && s < n) {
            int p = atomicAdd(&g_cursor[d], 1);
            if (p < EMAX) g_srcs[p] = s;
        }
    }
}

// ---------------- mma / ldmatrix helpers ----------------
__device__ __forceinline__ void mma16816(float* c, const uint32_t* a,
                                         uint32_t b0, uint32_t b1) {
    asm volatile(
        "mma.sync.aligned.m16n8k16.row.col.f32.bf16.bf16.f32 "
        "{%0,%1,%2,%3}, {%4,%5,%6,%7}, {%8,%9}, {%0,%1,%2,%3};"
        : "+f"(c[0]), "+f"(c[1]), "+f"(c[2]), "+f"(c[3])
        : "r"(a[0]), "r"(a[1]), "r"(a[2]), "r"(a[3]), "r"(b0), "r"(b1));
}

__device__ __forceinline__ void ldsm_x4(uint32_t* r, uint32_t addr) {
    asm volatile(
        "ldmatrix.sync.aligned.m8n8.x4.shared.b16 {%0,%1,%2,%3}, [%4];"
        : "=r"(r[0]), "=r"(r[1]), "=r"(r[2]), "=r"(r[3]) : "r"(addr));
}

__device__ __forceinline__ uint32_t smem_u32(const void* p) {
    uint32_t a;
    asm("{ .reg .u64 t; cvta.to.shared.u64 t, %1; cvt.u32.u64 %0, t; }"
        : "=r"(a) : "l"(p));
    return a;
}

__device__ __forceinline__ uint32_t pack_hi(float x, float y) {
    __nv_bfloat16 hx = __float2bfloat16_rn(x);
    __nv_bfloat16 hy = __float2bfloat16_rn(y);
    return ((uint32_t)__bfloat16_as_ushort(hy) << 16) | __bfloat16_as_ushort(hx);
}
__device__ __forceinline__ uint32_t pack_lo(float x, float y) {
    __nv_bfloat16 hx = __float2bfloat16_rn(x);
    __nv_bfloat16 hy = __float2bfloat16_rn(y);
    __nv_bfloat16 lx = __float2bfloat16_rn(x - __bfloat162float(hx));
    __nv_bfloat16 ly = __float2bfloat16_rn(y - __bfloat162float(hy));
    return ((uint32_t)__bfloat16_as_ushort(ly) << 16) | __bfloat16_as_ushort(lx);
}

// ---------------- pipelined fused SAGE layer -------------------------------
// out[m,:] = mean_{j in N(m)} X[j] @ Wl + X[m] @ Wr + b (+relu)
// fp32 via 3-term bf16 split: C = Ah*Bh + Al*Bh + Ah*Bl.
// 384 threads: warps 0-7 consumers (MMA, 4m x 2n, warp tile 32x64),
//              warps 8-11 producers (gather/convert A chunks, 32 rows each).
// Double-buffered A chunk smem; bulk-synchronous pipeline:
//   phase c: producers fill chunk c -> buf[c&1]; consumers MMA chunk c-1.
// Chunk map: c < CHUNKS/2 -> agg cols [c*64,..); else x cols [(c-CHUNKS/2)*64,..).
template <int CHUNKS, bool RELU>
__global__ __launch_bounds__(384, 1)
void sage_fused(const float* __restrict__ X, const unsigned short* __restrict__ Bimg,
                const float* __restrict__ bias, float* __restrict__ out,
                int n, int nTiles) {
    constexpr int D       = CHUNKS * 32;
    constexpr int STRIDEB = CHUNKS * 128 + 8;
    constexpr int KTOT    = CHUNKS * 64;
    constexpr int ASTRIDE = 136;

    extern __shared__ unsigned short sm[];
    unsigned short* As0 = sm;                       // 128*136
    unsigned short* As1 = sm + 128 * ASTRIDE;       // 128*136
    unsigned short* Bs  = sm + 2 * 128 * ASTRIDE;   // 128*STRIDEB

    const int tid  = threadIdx.x;
    const int wid  = tid >> 5;
    const int lane = tid & 31;

    // consumer geometry
    const int tq = lane >> 2;
    const int tr = lane & 3;
    const int wm = wid & 3;
    const int wn = (wid >> 2) & 1;
    const int g  = lane >> 3;
    const int lr = lane & 7;

    const uint32_t Bs_u  = smem_u32(Bs);
    const uint32_t aOff  = (uint32_t)(wm * 32 + (g & 1) * 8 + lr) * (ASTRIDE * 2)
                         + (uint32_t)((g >> 1) * 8) * 2;
    const uint32_t aBase0 = smem_u32(As0) + aOff;
    const uint32_t aBase1 = smem_u32(As1) + aOff;
    const uint32_t bBase  = Bs_u + (uint32_t)(wn * 64 + (g >> 1) * 8 + lr) * (STRIDEB * 2)
                                 + (uint32_t)((g & 1) * 8) * 2;

    // copy weight image into smem once (all 12 warps)
    {
        const float4* bsrc = (const float4*)Bimg;
        float4* bdst = (float4*)Bs;
        constexpr int NV = 128 * STRIDEB * 2 / 16;
        for (int i = tid; i < NV; i += 384) bdst[i] = bsrc[i];
    }

    float acc[2][8][4];

    auto mma_chunk = [&](int c, uint32_t aBase) {
#pragma unroll
        for (int ks = 0; ks < 4; ks++) {
            uint32_t ah[2][4], al[2][4], bh[4][4], bl[4][4];
#pragma unroll
            for (int ma = 0; ma < 2; ma++) {
                uint32_t a = aBase + (uint32_t)(ma * 16 * ASTRIDE * 2 + ks * 32);
                ldsm_x4(ah[ma], a);
                ldsm_x4(al[ma], a + 128);
            }
#pragma unroll
            for (int p = 0; p < 4; p++) {
                uint32_t b = bBase + (uint32_t)(p * 16 * STRIDEB * 2 + c * 128 + ks * 32);
                ldsm_x4(bh[p], b);
                ldsm_x4(bl[p], b + KTOT * 2);
            }
#pragma unroll
            for (int pass = 0; pass < 3; pass++) {
                const uint32_t (*Af)[4] = (pass == 1) ? al : ah;
                const uint32_t (*Bf)[4] = (pass == 2) ? bl : bh;
#pragma unroll
                for (int ma = 0; ma < 2; ma++)
#pragma unroll
                    for (int p = 0; p < 4; p++) {
                        mma16816(acc[ma][2 * p],     Af[ma], Bf[p][0], Bf[p][1]);
                        mma16816(acc[ma][2 * p + 1], Af[ma], Bf[p][2], Bf[p][3]);
                    }
            }
        }
    };

    auto epilogue = [&](int m0) {
#pragma unroll
        for (int ma = 0; ma < 2; ma++) {
            int row = m0 + wm * 32 + ma * 16 + tq;
#pragma unroll
            for (int nb = 0; nb < 8; nb++) {
                int col = wn * 64 + nb * 8 + 2 * tr;
                float2 bv = *(const float2*)(bias + col);
                if (row < n) {
                    float2 o;
                    o.x = acc[ma][nb][0] + bv.x;
                    o.y = acc[ma][nb][1] + bv.y;
                    if (RELU) { o.x = fmaxf(o.x, 0.0f); o.y = fmaxf(o.y, 0.0f); }
                    *(float2*)(out + (size_t)row * 128 + col) = o;
                }
                if (row + 8 < n) {
                    float2 o;
                    o.x = acc[ma][nb][2] + bv.x;
                    o.y = acc[ma][nb][3] + bv.y;
                    if (RELU) { o.x = fmaxf(o.x, 0.0f); o.y = fmaxf(o.y, 0.0f); }
                    *(float2*)(out + (size_t)(row + 8) * 128 + col) = o;
                }
            }
        }
    };

    // producer: fill chunk c of tile at m0 into buf
    auto produce = [&](int c, int m0, unsigned short* buf) {
        const int pw = wid - 8;              // 0..3
        if (c < CHUNKS / 2) {
            // agg chunk: cols [c*64, c*64+64)
            const int kb = c * 64;
            for (int i = 0; i < 32; i++) {
                int row  = pw * 32 + i;
                int node = min(m0 + row, n - 1);
                int jb = g_rowptr[node];
                int je = g_rowptr[node + 1];
                float ax = 0.f, ay = 0.f;
                int j = jb;
                for (; j + 1 < je; j += 2) {
                    int s0 = g_srcs[j], s1 = g_srcs[j + 1];
                    float2 v0 = __ldg((const float2*)(X + (size_t)s0 * D + kb + 2 * lane));
                    float2 v1 = __ldg((const float2*)(X + (size_t)s1 * D + kb + 2 * lane));
                    ax += v0.x + v1.x; ay += v0.y + v1.y;
                }
                if (j < je) {
                    int s0 = g_srcs[j];
                    float2 v0 = __ldg((const float2*)(X + (size_t)s0 * D + kb + 2 * lane));
                    ax += v0.x; ay += v0.y;
                }
                float inv = 1.0f / fmaxf((float)(je - jb), 1.0f);
                ax *= inv; ay *= inv;
                unsigned short* p = buf + row * ASTRIDE + 2 * lane;
                *(uint32_t*)(p)      = pack_hi(ax, ay);
                *(uint32_t*)(p + 64) = pack_lo(ax, ay);
            }
        } else {
            // x chunk: cols [(c-CHUNKS/2)*64, ...)
            const int kb = (c - CHUNKS / 2) * 64;
            for (int i = 0; i < 32; i++) {
                int row  = pw * 32 + i;
                int grow = min(m0 + row, n - 1);
                float2 v = *(const float2*)(X + (size_t)grow * D + kb + 2 * lane);
                unsigned short* p = buf + row * ASTRIDE + 2 * lane;
                *(uint32_t*)(p)      = pack_hi(v.x, v.y);
                *(uint32_t*)(p + 64) = pack_lo(v.x, v.y);
            }
        }
    };

    bool havePrev = false;
    int  prevM0   = 0;

    for (int tile = blockIdx.x; tile < nTiles; tile += gridDim.x) {
        const int m0 = tile * 128;
        for (int c = 0; c < CHUNKS; c++) {
            if (wid >= 8) {
                produce(c, m0, (c & 1) ? As1 : As0);
            } else {
                if (c == 0) {
                    if (havePrev) {
                        mma_chunk(CHUNKS - 1, ((CHUNKS - 1) & 1) ? aBase1 : aBase0);
                        epilogue(prevM0);
                    }
#pragma unroll
                    for (int a = 0; a < 2; a++)
#pragma unroll
                        for (int b = 0; b < 8; b++)
#pragma unroll
                            for (int q = 0; q < 4; q++) acc[a][b][q] = 0.0f;
                } else {
                    mma_chunk(c - 1, ((c - 1) & 1) ? aBase1 : aBase0);
                }
            }
            __syncthreads();
        }
        havePrev = true;
        prevM0 = m0;
    }
    // tail: last chunk + epilogue of the final tile
    if (wid < 8 && havePrev) {
        mma_chunk(CHUNKS - 1, ((CHUNKS - 1) & 1) ? aBase1 : aBase0);
        epilogue(prevM0);
    }
}

// ---------------- global mean pool ----------------
__global__ void pool_acc_kernel(const float* __restrict__ h,
                                const int* __restrict__ batch,
                                float* __restrict__ out, int n, int G) {
    const int NPW = 16;
    int gw   = (blockIdx.x * blockDim.x + threadIdx.x) >> 5;
    int lane = threadIdx.x & 31;
    int beg = gw * NPW;
    if (beg >= n) return;
    int end = min(beg + NPW, n);
    float a0 = 0, a1 = 0, a2 = 0, a3 = 0;
    int cur = min(max(batch[beg], 0), G - 1);
    int cnt = 0;
    for (int i = beg; i < end; i++) {
        int b = min(max(batch[i], 0), G - 1);
        if (b != cur) {
            atomicAdd(&out[cur * 128 + lane +  0], a0);
            atomicAdd(&out[cur * 128 + lane + 32], a1);
            atomicAdd(&out[cur * 128 + lane + 64], a2);
            atomicAdd(&out[cur * 128 + lane + 96], a3);
            if (lane == 0) atomicAdd(&g_gcnt[cur], (float)cnt);
            a0 = a1 = a2 = a3 = 0.0f;
            cnt = 0;
            cur = b;
        }
        const float* row = h + (size_t)i * 128;
        a0 += row[lane];      a1 += row[lane + 32];
        a2 += row[lane + 64]; a3 += row[lane + 96];
        cnt++;
    }
    atomicAdd(&out[cur * 128 + lane +  0], a0);
    atomicAdd(&out[cur * 128 + lane + 32], a1);
    atomicAdd(&out[cur * 128 + lane + 64], a2);
    atomicAdd(&out[cur * 128 + lane + 96], a3);
    if (lane == 0) atomicAdd(&g_gcnt[cur], (float)cnt);
}

__global__ void pool_div_kernel(float* out, int G) {
    int i = blockIdx.x * blockDim.x + threadIdx.x;
    if (i < G * 128) out[i] /= fmaxf(g_gcnt[i >> 7], 1.0f);
}

// ---------------- launch ----------------
extern "C" void kernel_launch(void* const* d_in, const int* in_sizes, int n_in,
                              void* d_out, int out_size) {
    const float* x     = (const float*)d_in[0];
    const int*   ei    = (const int*)d_in[1];
    const int*   batch = (const int*)d_in[2];
    const float* Wl1 = (const float*)d_in[3];
    const float* bl1 = (const float*)d_in[4];
    const float* Wr1 = (const float*)d_in[5];
    const float* Wl2 = (const float*)d_in[6];
    const float* bl2 = (const float*)d_in[7];
    const float* Wr2 = (const float*)d_in[8];
    const float* Wl3 = (const float*)d_in[9];
    const float* bl3 = (const float*)d_in[10];
    const float* Wr3 = (const float*)d_in[11];
    float* out = (float*)d_out;

    const int n = in_sizes[0] / 64;       // 50000
    const int E = in_sizes[1] / 2;        // 600000
    const int G = out_size / 128;         // 64

    const int* src = ei;
    const int* dst = ei + E;

    void *p_hA, *p_hB, *p_Bimg;
    cudaGetSymbolAddress(&p_hA, g_hA);
    cudaGetSymbolAddress(&p_hB, g_hB);
    cudaGetSymbolAddress(&p_Bimg, g_Bimg);
    float* hA  = (float*)p_hA;
    float* hB  = (float*)p_hB;
    unsigned short* Bimg = (unsigned short*)p_Bimg;

    const int smem1 = (2 * 128 * 136 + 128 * 264) * 2;   // 137216 (CHUNKS=2)
    const int smem2 = (2 * 128 * 136 + 128 * 520) * 2;   // 202752 (CHUNKS=4)
    cudaFuncSetAttribute(sage_fused<2, true >, cudaFuncAttributeMaxDynamicSharedMemorySize, smem1);
    cudaFuncSetAttribute(sage_fused<4, true >, cudaFuncAttributeMaxDynamicSharedMemorySize, smem2);
    cudaFuncSetAttribute(sage_fused<4, false>, cudaFuncAttributeMaxDynamicSharedMemorySize, smem2);

    // ---- setup: zero deg/out/gcnt + weight images (1 launch) ----
    {
        int total = n + G * 128 + G + 128 * 264 + 2 * (128 * 520);
        setup_kernel<<<(total + 255) / 256, 256>>>(Wl1, Wr1, Wl2, Wr2, Wl3, Wr3,
                                                   Bimg, out, n, G);
    }

    // ---- CSR build ----
    count_deg_kernel<<<(E + 255) / 256, 256>>>(dst, E, n);
    scan_kernel<<<1, 1024>>>(n);
    scatter_kernel<<<(E + 255) / 256, 256>>>(src, dst, E, n);

    const int nTiles = (n + 127) / 128;
    const int gemmGrid = 148;

    // ---- 3 pipelined fused SAGE layers ----
    sage_fused<2, true ><<<gemmGrid, 384, smem1>>>(x,  Bimg,          bl1, hA, n, nTiles);
    sage_fused<4, true ><<<gemmGrid, 384, smem2>>>(hA, Bimg + 33792,  bl2, hB, n, nTiles);
    sage_fused<4, false><<<gemmGrid, 384, smem2>>>(hB, Bimg + 100352, bl3, hA, n, nTiles);

    // ---- global mean pool ----
    int poolWarps = (n + 15) / 16;
    pool_acc_kernel<<<(poolWarps * 32 + 255) / 256, 256>>>(hA, batch, out, n, G);
    pool_div_kernel<<<(G * 128 + 255) / 256, 256>>>(out, G);
}

// round 10
// speedup vs baseline: 2.5591x; 2.5591x over previous
#include <cuda_runtime.h>
#include <cuda_bf16.h>
#include <cstdint>

// ---------------- problem constants ----------------
#define NMAX 50000
#define EMAX 600000
#define GMAX 256
#define DH 128

// ---------------- device scratch ----------------
__device__ float g_agg[(size_t)NMAX * DH];
__device__ float g_hA [(size_t)NMAX * DH];
__device__ float g_hB [(size_t)NMAX * DH];
__device__ int   g_deg[NMAX];
__device__ int   g_rowptr[NMAX + 1];
__device__ int   g_cursor[NMAX];
__device__ int   g_srcs[EMAX];
__device__ float g_gcnt[GMAX];
// pre-split bf16 hi/lo weight images, padded [n][2K+8] layout
__device__ unsigned short g_Bimg[167168];

// ---------------- fused setup: zero deg/out/gcnt + build 3 weight images ----
__device__ __forceinline__ void prep_B_elem(const float* Wl, const float* Wr,
                                            unsigned short* img, int chunks, int t) {
    int strideB = chunks * 128 + 8;
    int Ktot    = chunks * 64;
    int nn = t / strideB;
    int kk = t - nn * strideB;
    if (kk < Ktot) {
        int half = chunks * 32;
        const float* W; int k;
        if (kk < half) { W = Wl; k = kk; } else { W = Wr; k = kk - half; }
        float v = W[(size_t)k * 128 + nn];
        __nv_bfloat16 h = __float2bfloat16_rn(v);
        __nv_bfloat16 l = __float2bfloat16_rn(v - __bfloat162float(h));
        img[nn * strideB + kk]        = __bfloat16_as_ushort(h);
        img[nn * strideB + Ktot + kk] = __bfloat16_as_ushort(l);
    } else if (kk >= 2 * Ktot) {
        img[t] = 0;
    }
}

__global__ void setup_kernel(const float* __restrict__ Wl1, const float* __restrict__ Wr1,
                             const float* __restrict__ Wl2, const float* __restrict__ Wr2,
                             const float* __restrict__ Wl3, const float* __restrict__ Wr3,
                             unsigned short* __restrict__ img,
                             float* __restrict__ out, int n, int G) {
    const int s1 = n;
    const int s2 = s1 + G * 128;
    const int s3 = s2 + G;
    const int s4 = s3 + 128 * 264;
    const int s5 = s4 + 128 * 520;
    const int s6 = s5 + 128 * 520;
    for (int t = blockIdx.x * blockDim.x + threadIdx.x; t < s6;
         t += gridDim.x * blockDim.x) {
        if (t < s1)       g_deg[t] = 0;
        else if (t < s2)  out[t - s1] = 0.0f;
        else if (t < s3)  g_gcnt[t - s2] = 0.0f;
        else if (t < s4)  prep_B_elem(Wl1, Wr1, img,          2, t - s3);
        else if (t < s5)  prep_B_elem(Wl2, Wr2, img + 33792,  4, t - s4);
        else              prep_B_elem(Wl3, Wr3, img + 100352, 4, t - s5);
    }
}

// ---------------- CSR build (4 edges/thread, int4 loads) ----------------
__global__ void count_deg_kernel(const int* __restrict__ dst, int E, int n) {
    int t = blockIdx.x * blockDim.x + threadIdx.x;
    int e = 4 * t;
    if (e + 3 < E) {
        int4 d4 = *(const int4*)(dst + e);
        if (d4.x >= 0 && d4.x < n) atomicAdd(&g_deg[d4.x], 1);
        if (d4.y >= 0 && d4.y < n) atomicAdd(&g_deg[d4.y], 1);
        if (d4.z >= 0 && d4.z < n) atomicAdd(&g_deg[d4.z], 1);
        if (d4.w >= 0 && d4.w < n) atomicAdd(&g_deg[d4.w], 1);
    } else {
        for (int k = 0; k < 4; k++) {
            int ee = e + k;
            if (ee < E) {
                int d = dst[ee];
                if (d >= 0 && d < n) atomicAdd(&g_deg[d], 1);
            }
        }
    }
}

__global__ void scan_kernel(int n) {
    __shared__ int sh[1024];
    int tid = threadIdx.x;
    int chunk = (n + 1023) / 1024;
    int beg = tid * chunk;
    int end = min(beg + chunk, n);
    int s = 0;
    for (int i = beg; i < end; i++) s += g_deg[i];
    sh[tid] = s;
    __syncthreads();
    for (int off = 1; off < 1024; off <<= 1) {
        int v = (tid >= off) ? sh[tid - off] : 0;
        __syncthreads();
        sh[tid] += v;
        __syncthreads();
    }
    int run = sh[tid] - s;
    for (int i = beg; i < end; i++) {
        g_rowptr[i] = run;
        g_cursor[i] = run;
        run += g_deg[i];
    }
    if (tid == 1023) g_rowptr[n] = sh[1023];
}

__global__ void scatter_kernel(const int* __restrict__ src,
                               const int* __restrict__ dst, int E, int n) {
    int t = blockIdx.x * blockDim.x + threadIdx.x;
    int e = 4 * t;
    if (e + 3 < E) {
        int4 s4 = *(const int4*)(src + e);
        int4 d4 = *(const int4*)(dst + e);
        int p;
        if (d4.x >= 0 && d4.x < n && s4.x >= 0 && s4.x < n) {
            p = atomicAdd(&g_cursor[d4.x], 1); if (p < EMAX) g_srcs[p] = s4.x;
        }
        if (d4.y >= 0 && d4.y < n && s4.y >= 0 && s4.y < n) {
            p = atomicAdd(&g_cursor[d4.y], 1); if (p < EMAX) g_srcs[p] = s4.y;
        }
        if (d4.z >= 0 && d4.z < n && s4.z >= 0 && s4.z < n) {
            p = atomicAdd(&g_cursor[d4.z], 1); if (p < EMAX) g_srcs[p] = s4.z;
        }
        if (d4.w >= 0 && d4.w < n && s4.w >= 0 && s4.w < n) {
            p = atomicAdd(&g_cursor[d4.w], 1); if (p < EMAX) g_srcs[p] = s4.w;
        }
    } else {
        for (int k = 0; k < 4; k++) {
            int ee = e + k;
            if (ee < E) {
                int d = dst[ee];
                int s = src[ee];
                if (d >= 0 && d < n && s >= 0 && s < n) {
                    int p = atomicAdd(&g_cursor[d], 1);
                    if (p < EMAX) g_srcs[p] = s;
                }
            }
        }
    }
}

// ---------------- mean aggregation: one warp per node, MLP-4 gathers -------
template <int D>
__global__ void agg_kernel(const float* __restrict__ x, float* __restrict__ agg, int n) {
    int gw   = (blockIdx.x * blockDim.x + threadIdx.x) >> 5;
    int lane = threadIdx.x & 31;
    if (gw >= n) return;
    int beg = g_rowptr[gw];
    int end = g_rowptr[gw + 1];
    if (D == 128) {
        float4 acc = make_float4(0.f, 0.f, 0.f, 0.f);
        int j = beg;
        for (; j + 3 < end; j += 4) {
            // prefetch 4 indices, then 4 independent row gathers
            int s0 = g_srcs[j],     s1 = g_srcs[j + 1];
            int s2 = g_srcs[j + 2], s3 = g_srcs[j + 3];
            float4 v0 = __ldg((const float4*)(x + (size_t)s0 * D + 4 * lane));
            float4 v1 = __ldg((const float4*)(x + (size_t)s1 * D + 4 * lane));
            float4 v2 = __ldg((const float4*)(x + (size_t)s2 * D + 4 * lane));
            float4 v3 = __ldg((const float4*)(x + (size_t)s3 * D + 4 * lane));
            acc.x += (v0.x + v1.x) + (v2.x + v3.x);
            acc.y += (v0.y + v1.y) + (v2.y + v3.y);
            acc.z += (v0.z + v1.z) + (v2.z + v3.z);
            acc.w += (v0.w + v1.w) + (v2.w + v3.w);
        }
        for (; j < end; j++) {
            int s0 = g_srcs[j];
            float4 v0 = __ldg((const float4*)(x + (size_t)s0 * D + 4 * lane));
            acc.x += v0.x; acc.y += v0.y; acc.z += v0.z; acc.w += v0.w;
        }
        float inv = 1.0f / fmaxf((float)(end - beg), 1.0f);
        acc.x *= inv; acc.y *= inv; acc.z *= inv; acc.w *= inv;
        *(float4*)(agg + (size_t)gw * D + 4 * lane) = acc;
    } else {
        float2 acc = make_float2(0.f, 0.f);
        int j = beg;
        for (; j + 3 < end; j += 4) {
            int s0 = g_srcs[j],     s1 = g_srcs[j + 1];
            int s2 = g_srcs[j + 2], s3 = g_srcs[j + 3];
            float2 v0 = __ldg((const float2*)(x + (size_t)s0 * D + 2 * lane));
            float2 v1 = __ldg((const float2*)(x + (size_t)s1 * D + 2 * lane));
            float2 v2 = __ldg((const float2*)(x + (size_t)s2 * D + 2 * lane));
            float2 v3 = __ldg((const float2*)(x + (size_t)s3 * D + 2 * lane));
            acc.x += (v0.x + v1.x) + (v2.x + v3.x);
            acc.y += (v0.y + v1.y) + (v2.y + v3.y);
        }
        for (; j < end; j++) {
            int s0 = g_srcs[j];
            float2 v0 = __ldg((const float2*)(x + (size_t)s0 * D + 2 * lane));
            acc.x += v0.x; acc.y += v0.y;
        }
        float inv = 1.0f / fmaxf((float)(end - beg), 1.0f);
        acc.x *= inv; acc.y *= inv;
        *(float2*)(agg + (size_t)gw * D + 2 * lane) = acc;
    }
}

// ---------------- mma / ldmatrix helpers ----------------
__device__ __forceinline__ void mma16816(float* c, const uint32_t* a,
                                         uint32_t b0, uint32_t b1) {
    asm volatile(
        "mma.sync.aligned.m16n8k16.row.col.f32.bf16.bf16.f32 "
        "{%0,%1,%2,%3}, {%4,%5,%6,%7}, {%8,%9}, {%0,%1,%2,%3};"
        : "+f"(c[0]), "+f"(c[1]), "+f"(c[2]), "+f"(c[3])
        : "r"(a[0]), "r"(a[1]), "r"(a[2]), "r"(a[3]), "r"(b0), "r"(b1));
}

__device__ __forceinline__ void ldsm_x4(uint32_t* r, uint32_t addr) {
    asm volatile(
        "ldmatrix.sync.aligned.m8n8.x4.shared.b16 {%0,%1,%2,%3}, [%4];"
        : "=r"(r[0]), "=r"(r[1]), "=r"(r[2]), "=r"(r[3]) : "r"(addr));
}

__device__ __forceinline__ uint32_t smem_u32(const void* p) {
    uint32_t a;
    asm("{ .reg .u64 t; cvta.to.shared.u64 t, %1; cvt.u32.u64 %0, t; }"
        : "=r"(a) : "l"(p));
    return a;
}

// ---------------- persistent tensor-core fused SAGE GEMM ----------------
// out = [agg | x] @ [Wl;Wr] + b (+relu), fp32 via 3-term bf16 split.
// 512 threads, 16 warps (4 m x 4 n), warp tile 32x32, persistent grid=148.
template <int CHUNKS, bool RELU>
__global__ __launch_bounds__(512, 1)
void sage_mma(const float* __restrict__ A1, const float* __restrict__ A2,
              const unsigned short* __restrict__ Bimg, const float* __restrict__ bias,
              float* __restrict__ out, int n, int nTiles) {
    constexpr int STRIDEB = CHUNKS * 128 + 8;
    constexpr int KTOT    = CHUNKS * 64;
    constexpr int ASTRIDE = 136;
    constexpr int ASTR32  = CHUNKS * 32;

    extern __shared__ unsigned short sm[];
    unsigned short* As = sm;                    // 128 * 136
    unsigned short* Bs = sm + 128 * ASTRIDE;    // 128 * STRIDEB

    const int tid  = threadIdx.x;
    const int wid  = tid >> 5;
    const int lane = tid & 31;
    const int tq   = lane >> 2;
    const int tr   = lane & 3;
    const int wm   = wid & 3;
    const int wn   = wid >> 2;
    const int g    = lane >> 3;
    const int lr   = lane & 7;

    const uint32_t As_u = smem_u32(As);
    const uint32_t Bs_u = smem_u32(Bs);
    const uint32_t aBase = As_u + (uint32_t)(wm * 32 + (g & 1) * 8 + lr) * (ASTRIDE * 2)
                                + (uint32_t)((g >> 1) * 8) * 2;
    const uint32_t bBase = Bs_u + (uint32_t)(wn * 32 + (g >> 1) * 8 + lr) * (STRIDEB * 2)
                                + (uint32_t)((g & 1) * 8) * 2;

    {
        const float4* bsrc = (const float4*)Bimg;
        float4* bdst = (float4*)Bs;
        constexpr int NV = 128 * STRIDEB * 2 / 16;
        for (int i = tid; i < NV; i += 512) bdst[i] = bsrc[i];
    }

    for (int tile = blockIdx.x; tile < nTiles; tile += gridDim.x) {
        const int m0 = tile * 128;

        float acc[2][4][4];
#pragma unroll
        for (int a = 0; a < 2; a++)
#pragma unroll
            for (int b = 0; b < 4; b++)
#pragma unroll
                for (int q = 0; q < 4; q++) acc[a][b][q] = 0.0f;

        for (int c = 0; c < CHUNKS; ++c) {
            __syncthreads();

            const float* src = (c < CHUNKS / 2) ? A1 : A2;
            int kb = (c & (CHUNKS / 2 - 1)) * 64;
#pragma unroll
            for (int i = 0; i < 8; i++) {
                int p   = i * 512 + tid;
                int row = p >> 5;
                int k2  = p & 31;
                int grow = min(m0 + row, n - 1);
                float2 v = *(const float2*)(src + (size_t)grow * ASTR32 + kb + 2 * k2);
                __nv_bfloat16 h0 = __float2bfloat16_rn(v.x);
                __nv_bfloat16 h1 = __float2bfloat16_rn(v.y);
                __nv_bfloat16 l0 = __float2bfloat16_rn(v.x - __bfloat162float(h0));
                __nv_bfloat16 l1 = __float2bfloat16_rn(v.y - __bfloat162float(h1));
                uint32_t hp = ((uint32_t)__bfloat16_as_ushort(h1) << 16) | __bfloat16_as_ushort(h0);
                uint32_t lp = ((uint32_t)__bfloat16_as_ushort(l1) << 16) | __bfloat16_as_ushort(l0);
                *(uint32_t*)(As + row * ASTRIDE + 2 * k2)      = hp;
                *(uint32_t*)(As + row * ASTRIDE + 64 + 2 * k2) = lp;
            }
            __syncthreads();

#pragma unroll
            for (int ks = 0; ks < 4; ks++) {
                uint32_t ah[2][4], al[2][4], bh[2][4], bl[2][4];
#pragma unroll
                for (int ma = 0; ma < 2; ma++) {
                    uint32_t a = aBase + (uint32_t)(ma * 16 * ASTRIDE * 2 + ks * 32);
                    ldsm_x4(ah[ma], a);
                    ldsm_x4(al[ma], a + 128);
                }
#pragma unroll
                for (int p = 0; p < 2; p++) {
                    uint32_t b = bBase + (uint32_t)(p * 16 * STRIDEB * 2 + c * 128 + ks * 32);
                    ldsm_x4(bh[p], b);
                    ldsm_x4(bl[p], b + KTOT * 2);
                }
#pragma unroll
                for (int pass = 0; pass < 3; pass++) {
                    const uint32_t (*Af)[4] = (pass == 1) ? al : ah;
                    const uint32_t (*Bf)[4] = (pass == 2) ? bl : bh;
#pragma unroll
                    for (int ma = 0; ma < 2; ma++)
#pragma unroll
                        for (int p = 0; p < 2; p++) {
                            mma16816(acc[ma][2 * p],     Af[ma], Bf[p][0], Bf[p][1]);
                            mma16816(acc[ma][2 * p + 1], Af[ma], Bf[p][2], Bf[p][3]);
                        }
                }
            }
        }

#pragma unroll
        for (int ma = 0; ma < 2; ma++) {
            int row = m0 + wm * 32 + ma * 16 + tq;
#pragma unroll
            for (int nb = 0; nb < 4; nb++) {
                int col = wn * 32 + nb * 8 + 2 * tr;
                float2 bv = *(const float2*)(bias + col);
                if (row < n) {
                    float2 o;
                    o.x = acc[ma][nb][0] + bv.x;
                    o.y = acc[ma][nb][1] + bv.y;
                    if (RELU) { o.x = fmaxf(o.x, 0.0f); o.y = fmaxf(o.y, 0.0f); }
                    *(float2*)(out + (size_t)row * 128 + col) = o;
                }
                if (row + 8 < n) {
                    float2 o;
                    o.x = acc[ma][nb][2] + bv.x;
                    o.y = acc[ma][nb][3] + bv.y;
                    if (RELU) { o.x = fmaxf(o.x, 0.0f); o.y = fmaxf(o.y, 0.0f); }
                    *(float2*)(out + (size_t)(row + 8) * 128 + col) = o;
                }
            }
        }
    }
}

// ---------------- global mean pool ----------------
__global__ void pool_acc_kernel(const float* __restrict__ h,
                                const int* __restrict__ batch,
                                float* __restrict__ out, int n, int G) {
    const int NPW = 16;
    int gw   = (blockIdx.x * blockDim.x + threadIdx.x) >> 5;
    int lane = threadIdx.x & 31;
    int beg = gw * NPW;
    if (beg >= n) return;
    int end = min(beg + NPW, n);
    float a0 = 0, a1 = 0, a2 = 0, a3 = 0;
    int cur = min(max(batch[beg], 0), G - 1);
    int cnt = 0;
    for (int i = beg; i < end; i++) {
        int b = min(max(batch[i], 0), G - 1);
        if (b != cur) {
            atomicAdd(&out[cur * 128 + lane +  0], a0);
            atomicAdd(&out[cur * 128 + lane + 32], a1);
            atomicAdd(&out[cur * 128 + lane + 64], a2);
            atomicAdd(&out[cur * 128 + lane + 96], a3);
            if (lane == 0) atomicAdd(&g_gcnt[cur], (float)cnt);
            a0 = a1 = a2 = a3 = 0.0f;
            cnt = 0;
            cur = b;
        }
        const float* row = h + (size_t)i * 128;
        a0 += row[lane];      a1 += row[lane + 32];
        a2 += row[lane + 64]; a3 += row[lane + 96];
        cnt++;
    }
    atomicAdd(&out[cur * 128 + lane +  0], a0);
    atomicAdd(&out[cur * 128 + lane + 32], a1);
    atomicAdd(&out[cur * 128 + lane + 64], a2);
    atomicAdd(&out[cur * 128 + lane + 96], a3);
    if (lane == 0) atomicAdd(&g_gcnt[cur], (float)cnt);
}

__global__ void pool_div_kernel(float* out, int G) {
    int i = blockIdx.x * blockDim.x + threadIdx.x;
    if (i < G * 128) out[i] /= fmaxf(g_gcnt[i >> 7], 1.0f);
}

// ---------------- launch ----------------
extern "C" void kernel_launch(void* const* d_in, const int* in_sizes, int n_in,
                              void* d_out, int out_size) {
    const float* x     = (const float*)d_in[0];
    const int*   ei    = (const int*)d_in[1];
    const int*   batch = (const int*)d_in[2];
    const float* Wl1 = (const float*)d_in[3];
    const float* bl1 = (const float*)d_in[4];
    const float* Wr1 = (const float*)d_in[5];
    const float* Wl2 = (const float*)d_in[6];
    const float* bl2 = (const float*)d_in[7];
    const float* Wr2 = (const float*)d_in[8];
    const float* Wl3 = (const float*)d_in[9];
    const float* bl3 = (const float*)d_in[10];
    const float* Wr3 = (const float*)d_in[11];
    float* out = (float*)d_out;

    const int n = in_sizes[0] / 64;       // 50000
    const int E = in_sizes[1] / 2;        // 600000
    const int G = out_size / 128;         // 64

    const int* src = ei;
    const int* dst = ei + E;

    void *p_agg, *p_hA, *p_hB, *p_Bimg;
    cudaGetSymbolAddress(&p_agg, g_agg);
    cudaGetSymbolAddress(&p_hA, g_hA);
    cudaGetSymbolAddress(&p_hB, g_hB);
    cudaGetSymbolAddress(&p_Bimg, g_Bimg);
    float* agg = (float*)p_agg;
    float* hA  = (float*)p_hA;
    float* hB  = (float*)p_hB;
    unsigned short* Bimg = (unsigned short*)p_Bimg;

    const int smem1 = (128 * 136 + 128 * 264) * 2;   // 102400 (CHUNKS=2)
    const int smem2 = (128 * 136 + 128 * 520) * 2;   // 167936 (CHUNKS=4)
    cudaFuncSetAttribute(sage_mma<2, true >, cudaFuncAttributeMaxDynamicSharedMemorySize, smem1);
    cudaFuncSetAttribute(sage_mma<4, true >, cudaFuncAttributeMaxDynamicSharedMemorySize, smem2);
    cudaFuncSetAttribute(sage_mma<4, false>, cudaFuncAttributeMaxDynamicSharedMemorySize, smem2);

    // ---- setup: zero deg/out/gcnt + weight images (1 launch) ----
    {
        int total = n + G * 128 + G + 128 * 264 + 2 * (128 * 520);
        setup_kernel<<<(total + 255) / 256, 256>>>(Wl1, Wr1, Wl2, Wr2, Wl3, Wr3,
                                                   Bimg, out, n, G);
    }

    // ---- CSR build (4 edges/thread) ----
    int quads = (E + 3) / 4;
    count_deg_kernel<<<(quads + 255) / 256, 256>>>(dst, E, n);
    scan_kernel<<<1, 1024>>>(n);
    scatter_kernel<<<(quads + 255) / 256, 256>>>(src, dst, E, n);

    const int aggBlocks = (n * 32 + 255) / 256;
    const int nTiles = (n + 127) / 128;
    const int gemmGrid = 148;

    // ---- layer 1 ----
    agg_kernel<64><<<aggBlocks, 256>>>(x, agg, n);
    sage_mma<2, true><<<gemmGrid, 512, smem1>>>(agg, x, Bimg, bl1, hA, n, nTiles);

    // ---- layer 2 ----
    agg_kernel<128><<<aggBlocks, 256>>>(hA, agg, n);
    sage_mma<4, true><<<gemmGrid, 512, smem2>>>(agg, hA, Bimg + 33792, bl2, hB, n, nTiles);

    // ---- layer 3 ----
    agg_kernel<128><<<aggBlocks, 256>>>(hB, agg, n);
    sage_mma<4, false><<<gemmGrid, 512, smem2>>>(agg, hB, Bimg + 100352, bl3, hA, n, nTiles);

    // ---- global mean pool ----
    int poolWarps = (n + 15) / 16;
    pool_acc_kernel<<<(poolWarps * 32 + 255) / 256, 256>>>(hA, batch, out, n, G);
    pool_div_kernel<<<(G * 128 + 255) / 256, 256>>>(out, G);
}

// round 12
// speedup vs baseline: 2.5616x; 1.0010x over previous
#include <cuda_runtime.h>
#include <cuda_bf16.h>
#include <cstdint>

// ---------------- problem constants ----------------
#define NMAX 50000
#define EMAX 600000
#define GMAX 256
#define DH 128

// ---------------- device scratch ----------------
__device__ float g_agg[(size_t)NMAX * DH];
__device__ float g_hA [(size_t)NMAX * DH];
__device__ float g_hB [(size_t)NMAX * DH];
__device__ int   g_deg[NMAX];
__device__ int   g_rowptr[NMAX + 1];
__device__ int   g_cursor[NMAX];
__device__ int   g_srcs[EMAX];
__device__ float g_gcnt[GMAX];
// pre-split bf16 hi/lo weight images, padded [n][2K+8] layout
__device__ unsigned short g_Bimg[167168];

// ---------------- fused setup: zero deg/out/gcnt + build 3 weight images ----
__device__ __forceinline__ void prep_B_elem(const float* Wl, const float* Wr,
                                            unsigned short* img, int chunks, int t) {
    int strideB = chunks * 128 + 8;
    int Ktot    = chunks * 64;
    int nn = t / strideB;
    int kk = t - nn * strideB;
    if (kk < Ktot) {
        int half = chunks * 32;
        const float* W; int k;
        if (kk < half) { W = Wl; k = kk; } else { W = Wr; k = kk - half; }
        float v = W[(size_t)k * 128 + nn];
        __nv_bfloat16 h = __float2bfloat16_rn(v);
        __nv_bfloat16 l = __float2bfloat16_rn(v - __bfloat162float(h));
        img[nn * strideB + kk]        = __bfloat16_as_ushort(h);
        img[nn * strideB + Ktot + kk] = __bfloat16_as_ushort(l);
    } else if (kk >= 2 * Ktot) {
        img[t] = 0;
    }
}

__global__ void setup_kernel(const float* __restrict__ Wl1, const float* __restrict__ Wr1,
                             const float* __restrict__ Wl2, const float* __restrict__ Wr2,
                             const float* __restrict__ Wl3, const float* __restrict__ Wr3,
                             unsigned short* __restrict__ img,
                             float* __restrict__ out, int n, int G) {
    const int s1 = n;
    const int s2 = s1 + G * 128;
    const int s3 = s2 + G;
    const int s4 = s3 + 128 * 264;
    const int s5 = s4 + 128 * 520;
    const int s6 = s5 + 128 * 520;
    for (int t = blockIdx.x * blockDim.x + threadIdx.x; t < s6;
         t += gridDim.x * blockDim.x) {
        if (t < s1)       g_deg[t] = 0;
        else if (t < s2)  out[t - s1] = 0.0f;
        else if (t < s3)  g_gcnt[t - s2] = 0.0f;
        else if (t < s4)  prep_B_elem(Wl1, Wr1, img,          2, t - s3);
        else if (t < s5)  prep_B_elem(Wl2, Wr2, img + 33792,  4, t - s4);
        else              prep_B_elem(Wl3, Wr3, img + 100352, 4, t - s5);
    }
}

// ---------------- CSR build (4 edges/thread, int4 loads) ----------------
__global__ void count_deg_kernel(const int* __restrict__ dst, int E, int n) {
    int t = blockIdx.x * blockDim.x + threadIdx.x;
    int e = 4 * t;
    if (e + 3 < E) {
        int4 d4 = *(const int4*)(dst + e);
        if (d4.x >= 0 && d4.x < n) atomicAdd(&g_deg[d4.x], 1);
        if (d4.y >= 0 && d4.y < n) atomicAdd(&g_deg[d4.y], 1);
        if (d4.z >= 0 && d4.z < n) atomicAdd(&g_deg[d4.z], 1);
        if (d4.w >= 0 && d4.w < n) atomicAdd(&g_deg[d4.w], 1);
    } else {
        for (int k = 0; k < 4; k++) {
            int ee = e + k;
            if (ee < E) {
                int d = dst[ee];
                if (d >= 0 && d < n) atomicAdd(&g_deg[d], 1);
            }
        }
    }
}

__global__ void scan_kernel(int n) {
    __shared__ int sh[1024];
    int tid = threadIdx.x;
    int chunk = (n + 1023) / 1024;
    int beg = tid * chunk;
    int end = min(beg + chunk, n);
    int s = 0;
    for (int i = beg; i < end; i++) s += g_deg[i];
    sh[tid] = s;
    __syncthreads();
    for (int off = 1; off < 1024; off <<= 1) {
        int v = (tid >= off) ? sh[tid - off] : 0;
        __syncthreads();
        sh[tid] += v;
        __syncthreads();
    }
    int run = sh[tid] - s;
    for (int i = beg; i < end; i++) {
        g_rowptr[i] = run;
        g_cursor[i] = run;
        run += g_deg[i];
    }
    if (tid == 1023) g_rowptr[n] = sh[1023];
}

__global__ void scatter_kernel(const int* __restrict__ src,
                               const int* __restrict__ dst, int E, int n) {
    int t = blockIdx.x * blockDim.x + threadIdx.x;
    int e = 4 * t;
    if (e + 3 < E) {
        int4 s4 = *(const int4*)(src + e);
        int4 d4 = *(const int4*)(dst + e);
        int p;
        if (d4.x >= 0 && d4.x < n && s4.x >= 0 && s4.x < n) {
            p = atomicAdd(&g_cursor[d4.x], 1); if (p < EMAX) g_srcs[p] = s4.x;
        }
        if (d4.y >= 0 && d4.y < n && s4.y >= 0 && s4.y < n) {
            p = atomicAdd(&g_cursor[d4.y], 1); if (p < EMAX) g_srcs[p] = s4.y;
        }
        if (d4.z >= 0 && d4.z < n && s4.z >= 0 && s4.z < n) {
            p = atomicAdd(&g_cursor[d4.z], 1); if (p < EMAX) g_srcs[p] = s4.z;
        }
        if (d4.w >= 0 && d4.w < n && s4.w >= 0 && s4.w < n) {
            p = atomicAdd(&g_cursor[d4.w], 1); if (p < EMAX) g_srcs[p] = s4.w;
        }
    } else {
        for (int k = 0; k < 4; k++) {
            int ee = e + k;
            if (ee < E) {
                int d = dst[ee];
                int s = src[ee];
                if (d >= 0 && d < n && s >= 0 && s < n) {
                    int p = atomicAdd(&g_cursor[d], 1);
                    if (p < EMAX) g_srcs[p] = s;
                }
            }
        }
    }
}

// ---------------- mean aggregation: one warp per node, MLP-4 gathers -------
template <int D>
__global__ void agg_kernel(const float* __restrict__ x, float* __restrict__ agg, int n) {
    int gw   = (blockIdx.x * blockDim.x + threadIdx.x) >> 5;
    int lane = threadIdx.x & 31;
    if (gw >= n) return;
    int beg = g_rowptr[gw];
    int end = g_rowptr[gw + 1];
    if (D == 128) {
        float4 acc = make_float4(0.f, 0.f, 0.f, 0.f);
        int j = beg;
        for (; j + 3 < end; j += 4) {
            int s0 = g_srcs[j],     s1 = g_srcs[j + 1];
            int s2 = g_srcs[j + 2], s3 = g_srcs[j + 3];
            float4 v0 = __ldg((const float4*)(x + (size_t)s0 * D + 4 * lane));
            float4 v1 = __ldg((const float4*)(x + (size_t)s1 * D + 4 * lane));
            float4 v2 = __ldg((const float4*)(x + (size_t)s2 * D + 4 * lane));
            float4 v3 = __ldg((const float4*)(x + (size_t)s3 * D + 4 * lane));
            acc.x += (v0.x + v1.x) + (v2.x + v3.x);
            acc.y += (v0.y + v1.y) + (v2.y + v3.y);
            acc.z += (v0.z + v1.z) + (v2.z + v3.z);
            acc.w += (v0.w + v1.w) + (v2.w + v3.w);
        }
        for (; j < end; j++) {
            int s0 = g_srcs[j];
            float4 v0 = __ldg((const float4*)(x + (size_t)s0 * D + 4 * lane));
            acc.x += v0.x; acc.y += v0.y; acc.z += v0.z; acc.w += v0.w;
        }
        float inv = 1.0f / fmaxf((float)(end - beg), 1.0f);
        acc.x *= inv; acc.y *= inv; acc.z *= inv; acc.w *= inv;
        *(float4*)(agg + (size_t)gw * D + 4 * lane) = acc;
    } else {
        float2 acc = make_float2(0.f, 0.f);
        int j = beg;
        for (; j + 3 < end; j += 4) {
            int s0 = g_srcs[j],     s1 = g_srcs[j + 1];
            int s2 = g_srcs[j + 2], s3 = g_srcs[j + 3];
            float2 v0 = __ldg((const float2*)(x + (size_t)s0 * D + 2 * lane));
            float2 v1 = __ldg((const float2*)(x + (size_t)s1 * D + 2 * lane));
            float2 v2 = __ldg((const float2*)(x + (size_t)s2 * D + 2 * lane));
            float2 v3 = __ldg((const float2*)(x + (size_t)s3 * D + 2 * lane));
            acc.x += (v0.x + v1.x) + (v2.x + v3.x);
            acc.y += (v0.y + v1.y) + (v2.y + v3.y);
        }
        for (; j < end; j++) {
            int s0 = g_srcs[j];
            float2 v0 = __ldg((const float2*)(x + (size_t)s0 * D + 2 * lane));
            acc.x += v0.x; acc.y += v0.y;
        }
        float inv = 1.0f / fmaxf((float)(end - beg), 1.0f);
        acc.x *= inv; acc.y *= inv;
        *(float2*)(agg + (size_t)gw * D + 2 * lane) = acc;
    }
}

// ---------------- mma / ldmatrix helpers ----------------
__device__ __forceinline__ void mma16816(float* c, const uint32_t* a,
                                         uint32_t b0, uint32_t b1) {
    asm volatile(
        "mma.sync.aligned.m16n8k16.row.col.f32.bf16.bf16.f32 "
        "{%0,%1,%2,%3}, {%4,%5,%6,%7}, {%8,%9}, {%0,%1,%2,%3};"
        : "+f"(c[0]), "+f"(c[1]), "+f"(c[2]), "+f"(c[3])
        : "r"(a[0]), "r"(a[1]), "r"(a[2]), "r"(a[3]), "r"(b0), "r"(b1));
}

__device__ __forceinline__ void ldsm_x4(uint32_t* r, uint32_t addr) {
    asm volatile(
        "ldmatrix.sync.aligned.m8n8.x4.shared.b16 {%0,%1,%2,%3}, [%4];"
        : "=r"(r[0]), "=r"(r[1]), "=r"(r[2]), "=r"(r[3]) : "r"(addr));
}

__device__ __forceinline__ uint32_t smem_u32(const void* p) {
    uint32_t a;
    asm("{ .reg .u64 t; cvta.to.shared.u64 t, %1; cvt.u32.u64 %0, t; }"
        : "=r"(a) : "l"(p));
    return a;
}

// ---------------- persistent tensor-core fused SAGE GEMM ----------------
// out = [agg | x] @ [Wl;Wr] + b (+relu), fp32 via 3-term bf16 split.
// 512 threads, 16 warps (4 m x 4 n), warp tile 32x32, persistent grid=148.
// Software pipeline: A chunk c+1 prefetched into registers during MMA of chunk c.
template <int CHUNKS, bool RELU>
__global__ __launch_bounds__(512, 1)
void sage_mma(const float* __restrict__ A1, const float* __restrict__ A2,
              const unsigned short* __restrict__ Bimg, const float* __restrict__ bias,
              float* __restrict__ out, int n, int nTiles) {
    constexpr int STRIDEB = CHUNKS * 128 + 8;
    constexpr int KTOT    = CHUNKS * 64;
    constexpr int ASTRIDE = 136;
    constexpr int ASTR32  = CHUNKS * 32;

    extern __shared__ unsigned short sm[];
    unsigned short* As = sm;                    // 128 * 136
    unsigned short* Bs = sm + 128 * ASTRIDE;    // 128 * STRIDEB

    const int tid  = threadIdx.x;
    const int wid  = tid >> 5;
    const int lane = tid & 31;
    const int tq   = lane >> 2;
    const int tr   = lane & 3;
    const int wm   = wid & 3;
    const int wn   = wid >> 2;
    const int g    = lane >> 3;
    const int lr   = lane & 7;

    const uint32_t As_u = smem_u32(As);
    const uint32_t Bs_u = smem_u32(Bs);
    const uint32_t aBase = As_u + (uint32_t)(wm * 32 + (g & 1) * 8 + lr) * (ASTRIDE * 2)
                                + (uint32_t)((g >> 1) * 8) * 2;
    const uint32_t bBase = Bs_u + (uint32_t)(wn * 32 + (g >> 1) * 8 + lr) * (STRIDEB * 2)
                                + (uint32_t)((g & 1) * 8) * 2;

    {
        const float4* bsrc = (const float4*)Bimg;
        float4* bdst = (float4*)Bs;
        constexpr int NV = 128 * STRIDEB * 2 / 16;
        for (int i = tid; i < NV; i += 512) bdst[i] = bsrc[i];
    }

    // per-thread A-load geometry: thread covers rows (i*512+tid)>>5, cols 2*((..)&31)
    const int lrow0 = tid >> 5;     // + 16*i
    const int lk2   = (tid & 31) * 2;

    float2 v[8];
    auto load_chunk = [&](int m0, int c) {
        const float* src = (c < CHUNKS / 2) ? A1 : A2;
        int kb = (c & (CHUNKS / 2 - 1)) * 64;
#pragma unroll
        for (int i = 0; i < 8; i++) {
            int grow = min(m0 + lrow0 + 16 * i, n - 1);
            v[i] = *(const float2*)(src + (size_t)grow * ASTR32 + kb + lk2);
        }
    };

    int tile = blockIdx.x;
    if (tile < nTiles) load_chunk(tile * 128, 0);

    for (; tile < nTiles; tile += gridDim.x) {
        const int m0 = tile * 128;

        float acc[2][4][4];
#pragma unroll
        for (int a = 0; a < 2; a++)
#pragma unroll
            for (int b = 0; b < 4; b++)
#pragma unroll
                for (int q = 0; q < 4; q++) acc[a][b][q] = 0.0f;

        for (int c = 0; c < CHUNKS; ++c) {
            __syncthreads();   // previous MMA done reading As

            // convert prefetched registers -> hi/lo bf16 in smem
#pragma unroll
            for (int i = 0; i < 8; i++) {
                int row = lrow0 + 16 * i;
                __nv_bfloat16 h0 = __float2bfloat16_rn(v[i].x);
                __nv_bfloat16 h1 = __float2bfloat16_rn(v[i].y);
                __nv_bfloat16 l0 = __float2bfloat16_rn(v[i].x - __bfloat162float(h0));
                __nv_bfloat16 l1 = __float2bfloat16_rn(v[i].y - __bfloat162float(h1));
                uint32_t hp = ((uint32_t)__bfloat16_as_ushort(h1) << 16) | __bfloat16_as_ushort(h0);
                uint32_t lp = ((uint32_t)__bfloat16_as_ushort(l1) << 16) | __bfloat16_as_ushort(l0);
                *(uint32_t*)(As + row * ASTRIDE + lk2)      = hp;
                *(uint32_t*)(As + row * ASTRIDE + 64 + lk2) = lp;
            }

            // prefetch next chunk (possibly next tile's chunk 0); latency
            // hidden behind the sync + MMA phase below
            {
                int nc = c + 1, nt = tile;
                if (nc == CHUNKS) { nc = 0; nt = tile + gridDim.x; }
                if (nt < nTiles) load_chunk(nt * 128, nc);
            }
            __syncthreads();   // As ready

#pragma unroll
            for (int ks = 0; ks < 4; ks++) {
                uint32_t ah[2][4], al[2][4], bh[2][4], bl[2][4];
#pragma unroll
                for (int ma = 0; ma < 2; ma++) {
                    uint32_t a = aBase + (uint32_t)(ma * 16 * ASTRIDE * 2 + ks * 32);
                    ldsm_x4(ah[ma], a);
                    ldsm_x4(al[ma], a + 128);
                }
#pragma unroll
                for (int p = 0; p < 2; p++) {
                    uint32_t b = bBase + (uint32_t)(p * 16 * STRIDEB * 2 + c * 128 + ks * 32);
                    ldsm_x4(bh[p], b);
                    ldsm_x4(bl[p], b + KTOT * 2);
                }
#pragma unroll
                for (int pass = 0; pass < 3; pass++) {
                    const uint32_t (*Af)[4] = (pass == 1) ? al : ah;
                    const uint32_t (*Bf)[4] = (pass == 2) ? bl : bh;
#pragma unroll
                    for (int ma = 0; ma < 2; ma++)
#pragma unroll
                        for (int p = 0; p < 2; p++) {
                            mma16816(acc[ma][2 * p],     Af[ma], Bf[p][0], Bf[p][1]);
                            mma16816(acc[ma][2 * p + 1], Af[ma], Bf[p][2], Bf[p][3]);
                        }
                }
            }
        }

#pragma unroll
        for (int ma = 0; ma < 2; ma++) {
            int row = m0 + wm * 32 + ma * 16 + tq;
#pragma unroll
            for (int nb = 0; nb < 4; nb++) {
                int col = wn * 32 + nb * 8 + 2 * tr;
                float2 bv = *(const float2*)(bias + col);
                if (row < n) {
                    float2 o;
                    o.x = acc[ma][nb][0] + bv.x;
                    o.y = acc[ma][nb][1] + bv.y;
                    if (RELU) { o.x = fmaxf(o.x, 0.0f); o.y = fmaxf(o.y, 0.0f); }
                    *(float2*)(out + (size_t)row * 128 + col) = o;
                }
                if (row + 8 < n) {
                    float2 o;
                    o.x = acc[ma][nb][2] + bv.x;
                    o.y = acc[ma][nb][3] + bv.y;
                    if (RELU) { o.x = fmaxf(o.x, 0.0f); o.y = fmaxf(o.y, 0.0f); }
                    *(float2*)(out + (size_t)(row + 8) * 128 + col) = o;
                }
            }
        }
    }
}

// ---------------- global mean pool ----------------
__global__ void pool_acc_kernel(const float* __restrict__ h,
                                const int* __restrict__ batch,
                                float* __restrict__ out, int n, int G) {
    const int NPW = 16;
    int gw   = (blockIdx.x * blockDim.x + threadIdx.x) >> 5;
    int lane = threadIdx.x & 31;
    int beg = gw * NPW;
    if (beg >= n) return;
    int end = min(beg + NPW, n);
    float a0 = 0, a1 = 0, a2 = 0, a3 = 0;
    int cur = min(max(batch[beg], 0), G - 1);
    int cnt = 0;
    for (int i = beg; i < end; i++) {
        int b = min(max(batch[i], 0), G - 1);
        if (b != cur) {
            atomicAdd(&out[cur * 128 + lane +  0], a0);
            atomicAdd(&out[cur * 128 + lane + 32], a1);
            atomicAdd(&out[cur * 128 + lane + 64], a2);
            atomicAdd(&out[cur * 128 + lane + 96], a3);
            if (lane == 0) atomicAdd(&g_gcnt[cur], (float)cnt);
            a0 = a1 = a2 = a3 = 0.0f;
            cnt = 0;
            cur = b;
        }
        const float* row = h + (size_t)i * 128;
        a0 += row[lane];      a1 += row[lane + 32];
        a2 += row[lane + 64]; a3 += row[lane + 96];
        cnt++;
    }
    atomicAdd(&out[cur * 128 + lane +  0], a0);
    atomicAdd(&out[cur * 128 + lane + 32], a1);
    atomicAdd(&out[cur * 128 + lane + 64], a2);
    atomicAdd(&out[cur * 128 + lane + 96], a3);
    if (lane == 0) atomicAdd(&g_gcnt[cur], (float)cnt);
}

__global__ void pool_div_kernel(float* out, int G) {
    int i = blockIdx.x * blockDim.x + threadIdx.x;
    if (i < G * 128) out[i] /= fmaxf(g_gcnt[i >> 7], 1.0f);
}

// ---------------- launch ----------------
extern "C" void kernel_launch(void* const* d_in, const int* in_sizes, int n_in,
                              void* d_out, int out_size) {
    const float* x     = (const float*)d_in[0];
    const int*   ei    = (const int*)d_in[1];
    const int*   batch = (const int*)d_in[2];
    const float* Wl1 = (const float*)d_in[3];
    const float* bl1 = (const float*)d_in[4];
    const float* Wr1 = (const float*)d_in[5];
    const float* Wl2 = (const float*)d_in[6];
    const float* bl2 = (const float*)d_in[7];
    const float* Wr2 = (const float*)d_in[8];
    const float* Wl3 = (const float*)d_in[9];
    const float* bl3 = (const float*)d_in[10];
    const float* Wr3 = (const float*)d_in[11];
    float* out = (float*)d_out;

    const int n = in_sizes[0] / 64;       // 50000
    const int E = in_sizes[1] / 2;        // 600000
    const int G = out_size / 128;         // 64

    const int* src = ei;
    const int* dst = ei + E;

    void *p_agg, *p_hA, *p_hB, *p_Bimg;
    cudaGetSymbolAddress(&p_agg, g_agg);
    cudaGetSymbolAddress(&p_hA, g_hA);
    cudaGetSymbolAddress(&p_hB, g_hB);
    cudaGetSymbolAddress(&p_Bimg, g_Bimg);
    float* agg = (float*)p_agg;
    float* hA  = (float*)p_hA;
    float* hB  = (float*)p_hB;
    unsigned short* Bimg = (unsigned short*)p_Bimg;

    const int smem1 = (128 * 136 + 128 * 264) * 2;   // 102400 (CHUNKS=2)
    const int smem2 = (128 * 136 + 128 * 520) * 2;   // 167936 (CHUNKS=4)
    cudaFuncSetAttribute(sage_mma<2, true >, cudaFuncAttributeMaxDynamicSharedMemorySize, smem1);
    cudaFuncSetAttribute(sage_mma<4, true >, cudaFuncAttributeMaxDynamicSharedMemorySize, smem2);
    cudaFuncSetAttribute(sage_mma<4, false>, cudaFuncAttributeMaxDynamicSharedMemorySize, smem2);

    // ---- setup: zero deg/out/gcnt + weight images (1 launch) ----
    {
        int total = n + G * 128 + G + 128 * 264 + 2 * (128 * 520);
        setup_kernel<<<(total + 255) / 256, 256>>>(Wl1, Wr1, Wl2, Wr2, Wl3, Wr3,
                                                   Bimg, out, n, G);
    }

    // ---- CSR build (4 edges/thread) ----
    int quads = (E + 3) / 4;
    count_deg_kernel<<<(quads + 255) / 256, 256>>>(dst, E, n);
    scan_kernel<<<1, 1024>>>(n);
    scatter_kernel<<<(quads + 255) / 256, 256>>>(src, dst, E, n);

    const int aggBlocks = (n * 32 + 255) / 256;
    const int nTiles = (n + 127) / 128;
    const int gemmGrid = 148;

    // ---- layer 1 ----
    agg_kernel<64><<<aggBlocks, 256>>>(x, agg, n);
    sage_mma<2, true><<<gemmGrid, 512, smem1>>>(agg, x, Bimg, bl1, hA, n, nTiles);

    // ---- layer 2 ----
    agg_kernel<128><<<aggBlocks, 256>>>(hA, agg, n);
    sage_mma<4, true><<<gemmGrid, 512, smem2>>>(agg, hA, Bimg + 33792, bl2, hB, n, nTiles);

    // ---- layer 3 ----
    agg_kernel<128><<<aggBlocks, 256>>>(hB, agg, n);
    sage_mma<4, false><<<gemmGrid, 512, smem2>>>(agg, hB, Bimg + 100352, bl3, hA, n, nTiles);

    // ---- global mean pool ----
    int poolWarps = (n + 15) / 16;
    pool_acc_kernel<<<(poolWarps * 32 + 255) / 256, 256>>>(hA, batch, out, n, G);
    pool_div_kernel<<<(G * 128 + 255) / 256, 256>>>(out, G);
}

// round 13
// speedup vs baseline: 2.5798x; 1.0071x over previous
#include <cuda_runtime.h>
#include <cuda_bf16.h>
#include <cstdint>

// ---------------- problem constants ----------------
#define NMAX 50000
#define EMAX 600000
#define GMAX 256
#define DH 128

// ---------------- device scratch ----------------
// g_deg / g_cursor rely on static zero-init at load; every kernel_launch call
// restores them to zero at the end (pool_div), so the precondition holds for
// the correctness run and for every graph replay.
__device__ float g_agg[(size_t)NMAX * DH];
__device__ float g_hA [(size_t)NMAX * DH];
__device__ float g_hB [(size_t)NMAX * DH];
__device__ int   g_deg[NMAX];
__device__ int   g_rowptr[NMAX + 1];
__device__ int   g_cursor[NMAX];
__device__ int   g_srcs[EMAX];
__device__ float g_gcnt[GMAX];
// pre-split bf16 hi/lo weight images, padded [n][2K+8] layout
__device__ unsigned short g_Bimg[167168];

// ---------------- setup: zero out/gcnt + build 3 weight images ----------
__device__ __forceinline__ void prep_B_elem(const float* Wl, const float* Wr,
                                            unsigned short* img, int chunks, int t) {
    int strideB = chunks * 128 + 8;
    int Ktot    = chunks * 64;
    int nn = t / strideB;
    int kk = t - nn * strideB;
    if (kk < Ktot) {
        int half = chunks * 32;
        const float* W; int k;
        if (kk < half) { W = Wl; k = kk; } else { W = Wr; k = kk - half; }
        float v = W[(size_t)k * 128 + nn];
        __nv_bfloat16 h = __float2bfloat16_rn(v);
        __nv_bfloat16 l = __float2bfloat16_rn(v - __bfloat162float(h));
        img[nn * strideB + kk]        = __bfloat16_as_ushort(h);
        img[nn * strideB + Ktot + kk] = __bfloat16_as_ushort(l);
    } else if (kk >= 2 * Ktot) {
        img[t] = 0;
    }
}

__global__ void setup_kernel(const float* __restrict__ Wl1, const float* __restrict__ Wr1,
                             const float* __restrict__ Wl2, const float* __restrict__ Wr2,
                             const float* __restrict__ Wl3, const float* __restrict__ Wr3,
                             unsigned short* __restrict__ img,
                             float* __restrict__ out, int G) {
    const int s2 = G * 128;            // out zero
    const int s3 = s2 + G;             // gcnt zero
    const int s4 = s3 + 128 * 264;     // B1
    const int s5 = s4 + 128 * 520;     // B2
    const int s6 = s5 + 128 * 520;     // B3
    for (int t = blockIdx.x * blockDim.x + threadIdx.x; t < s6;
         t += gridDim.x * blockDim.x) {
        if (t < s2)       out[t] = 0.0f;
        else if (t < s3)  g_gcnt[t - s2] = 0.0f;
        else if (t < s4)  prep_B_elem(Wl1, Wr1, img,          2, t - s3);
        else if (t < s5)  prep_B_elem(Wl2, Wr2, img + 33792,  4, t - s4);
        else              prep_B_elem(Wl3, Wr3, img + 100352, 4, t - s5);
    }
}

// ---------------- CSR build (4 edges/thread, int4 loads) ----------------
// Precondition: g_deg == 0 (static init / restored by pool_div).
__global__ void count_deg_kernel(const int* __restrict__ dst, int E, int n) {
    int t = blockIdx.x * blockDim.x + threadIdx.x;
    int e = 4 * t;
    if (e + 3 < E) {
        int4 d4 = *(const int4*)(dst + e);
        if (d4.x >= 0 && d4.x < n) atomicAdd(&g_deg[d4.x], 1);
        if (d4.y >= 0 && d4.y < n) atomicAdd(&g_deg[d4.y], 1);
        if (d4.z >= 0 && d4.z < n) atomicAdd(&g_deg[d4.z], 1);
        if (d4.w >= 0 && d4.w < n) atomicAdd(&g_deg[d4.w], 1);
    } else {
        for (int k = 0; k < 4; k++) {
            int ee = e + k;
            if (ee < E) {
                int d = dst[ee];
                if (d >= 0 && d < n) atomicAdd(&g_deg[d], 1);
            }
        }
    }
}

// exclusive scan deg -> rowptr; cursor gets rowptr (base offsets)
__global__ void scan_kernel(int n) {
    __shared__ int sh[1024];
    int tid = threadIdx.x;
    int chunk = (n + 1023) / 1024;
    int beg = tid * chunk;
    int end = min(beg + chunk, n);
    int s = 0;
    for (int i = beg; i < end; i++) s += g_deg[i];
    sh[tid] = s;
    __syncthreads();
    for (int off = 1; off < 1024; off <<= 1) {
        int v = (tid >= off) ? sh[tid - off] : 0;
        __syncthreads();
        sh[tid] += v;
        __syncthreads();
    }
    int run = sh[tid] - s;
    for (int i = beg; i < end; i++) {
        g_rowptr[i] = run;
        g_cursor[i] = run;
        run += g_deg[i];
    }
    if (tid == 1023) g_rowptr[n] = sh[1023];
}

__global__ void scatter_kernel(const int* __restrict__ src,
                               const int* __restrict__ dst, int E, int n) {
    int t = blockIdx.x * blockDim.x + threadIdx.x;
    int e = 4 * t;
    if (e + 3 < E) {
        int4 s4 = *(const int4*)(src + e);
        int4 d4 = *(const int4*)(dst + e);
        int p;
        if (d4.x >= 0 && d4.x < n && s4.x >= 0 && s4.x < n) {
            p = atomicAdd(&g_cursor[d4.x], 1); if (p < EMAX) g_srcs[p] = s4.x;
        }
        if (d4.y >= 0 && d4.y < n && s4.y >= 0 && s4.y < n) {
            p = atomicAdd(&g_cursor[d4.y], 1); if (p < EMAX) g_srcs[p] = s4.y;
        }
        if (d4.z >= 0 && d4.z < n && s4.z >= 0 && s4.z < n) {
            p = atomicAdd(&g_cursor[d4.z], 1); if (p < EMAX) g_srcs[p] = s4.z;
        }
        if (d4.w >= 0 && d4.w < n && s4.w >= 0 && s4.w < n) {
            p = atomicAdd(&g_cursor[d4.w], 1); if (p < EMAX) g_srcs[p] = s4.w;
        }
    } else {
        for (int k = 0; k < 4; k++) {
            int ee = e + k;
            if (ee < E) {
                int d = dst[ee];
                int s = src[ee];
                if (d >= 0 && d < n && s >= 0 && s < n) {
                    int p = atomicAdd(&g_cursor[d], 1);
                    if (p < EMAX) g_srcs[p] = s;
                }
            }
        }
    }
}

// ---------------- mean aggregation: one warp per node, MLP-4 gathers -------
template <int D>
__global__ void agg_kernel(const float* __restrict__ x, float* __restrict__ agg, int n) {
    int gw   = (blockIdx.x * blockDim.x + threadIdx.x) >> 5;
    int lane = threadIdx.x & 31;
    if (gw >= n) return;
    int beg = g_rowptr[gw];
    int end = g_rowptr[gw + 1];
    if (D == 128) {
        float4 acc = make_float4(0.f, 0.f, 0.f, 0.f);
        int j = beg;
        for (; j + 3 < end; j += 4) {
            int s0 = g_srcs[j],     s1 = g_srcs[j + 1];
            int s2 = g_srcs[j + 2], s3 = g_srcs[j + 3];
            float4 v0 = __ldg((const float4*)(x + (size_t)s0 * D + 4 * lane));
            float4 v1 = __ldg((const float4*)(x + (size_t)s1 * D + 4 * lane));
            float4 v2 = __ldg((const float4*)(x + (size_t)s2 * D + 4 * lane));
            float4 v3 = __ldg((const float4*)(x + (size_t)s3 * D + 4 * lane));
            acc.x += (v0.x + v1.x) + (v2.x + v3.x);
            acc.y += (v0.y + v1.y) + (v2.y + v3.y);
            acc.z += (v0.z + v1.z) + (v2.z + v3.z);
            acc.w += (v0.w + v1.w) + (v2.w + v3.w);
        }
        for (; j < end; j++) {
            int s0 = g_srcs[j];
            float4 v0 = __ldg((const float4*)(x + (size_t)s0 * D + 4 * lane));
            acc.x += v0.x; acc.y += v0.y; acc.z += v0.z; acc.w += v0.w;
        }
        float inv = 1.0f / fmaxf((float)(end - beg), 1.0f);
        acc.x *= inv; acc.y *= inv; acc.z *= inv; acc.w *= inv;
        *(float4*)(agg + (size_t)gw * D + 4 * lane) = acc;
    } else {
        float2 acc = make_float2(0.f, 0.f);
        int j = beg;
        for (; j + 3 < end; j += 4) {
            int s0 = g_srcs[j],     s1 = g_srcs[j + 1];
            int s2 = g_srcs[j + 2], s3 = g_srcs[j + 3];
            float2 v0 = __ldg((const float2*)(x + (size_t)s0 * D + 2 * lane));
            float2 v1 = __ldg((const float2*)(x + (size_t)s1 * D + 2 * lane));
            float2 v2 = __ldg((const float2*)(x + (size_t)s2 * D + 2 * lane));
            float2 v3 = __ldg((const float2*)(x + (size_t)s3 * D + 2 * lane));
            acc.x += (v0.x + v1.x) + (v2.x + v3.x);
            acc.y += (v0.y + v1.y) + (v2.y + v3.y);
        }
        for (; j < end; j++) {
            int s0 = g_srcs[j];
            float2 v0 = __ldg((const float2*)(x + (size_t)s0 * D + 2 * lane));
            acc.x += v0.x; acc.y += v0.y;
        }
        float inv = 1.0f / fmaxf((float)(end - beg), 1.0f);
        acc.x *= inv; acc.y *= inv;
        *(float2*)(agg + (size_t)gw * D + 2 * lane) = acc;
    }
}

// ---------------- mma / ldmatrix helpers ----------------
__device__ __forceinline__ void mma16816(float* c, const uint32_t* a,
                                         uint32_t b0, uint32_t b1) {
    asm volatile(
        "mma.sync.aligned.m16n8k16.row.col.f32.bf16.bf16.f32 "
        "{%0,%1,%2,%3}, {%4,%5,%6,%7}, {%8,%9}, {%0,%1,%2,%3};"
        : "+f"(c[0]), "+f"(c[1]), "+f"(c[2]), "+f"(c[3])
        : "r"(a[0]), "r"(a[1]), "r"(a[2]), "r"(a[3]), "r"(b0), "r"(b1));
}

__device__ __forceinline__ void ldsm_x4(uint32_t* r, uint32_t addr) {
    asm volatile(
        "ldmatrix.sync.aligned.m8n8.x4.shared.b16 {%0,%1,%2,%3}, [%4];"
        : "=r"(r[0]), "=r"(r[1]), "=r"(r[2]), "=r"(r[3]) : "r"(addr));
}

__device__ __forceinline__ uint32_t smem_u32(const void* p) {
    uint32_t a;
    asm("{ .reg .u64 t; cvta.to.shared.u64 t, %1; cvt.u32.u64 %0, t; }"
        : "=r"(a) : "l"(p));
    return a;
}

// ---------------- persistent tensor-core fused SAGE GEMM ----------------
// out = [agg | x] @ [Wl;Wr] + b (+relu), fp32 via 3-term bf16 split.
// 512 threads, 16 warps (4 m x 4 n), warp tile 32x32, persistent grid=148.
// Software pipeline: A chunk c+1 prefetched into registers during MMA of chunk c.
template <int CHUNKS, bool RELU>
__global__ __launch_bounds__(512, 1)
void sage_mma(const float* __restrict__ A1, const float* __restrict__ A2,
              const unsigned short* __restrict__ Bimg, const float* __restrict__ bias,
              float* __restrict__ out, int n, int nTiles) {
    constexpr int STRIDEB = CHUNKS * 128 + 8;
    constexpr int KTOT    = CHUNKS * 64;
    constexpr int ASTRIDE = 136;
    constexpr int ASTR32  = CHUNKS * 32;

    extern __shared__ unsigned short sm[];
    unsigned short* As = sm;                    // 128 * 136
    unsigned short* Bs = sm + 128 * ASTRIDE;    // 128 * STRIDEB

    const int tid  = threadIdx.x;
    const int wid  = tid >> 5;
    const int lane = tid & 31;
    const int tq   = lane >> 2;
    const int tr   = lane & 3;
    const int wm   = wid & 3;
    const int wn   = wid >> 2;
    const int g    = lane >> 3;
    const int lr   = lane & 7;

    const uint32_t As_u = smem_u32(As);
    const uint32_t Bs_u = smem_u32(Bs);
    const uint32_t aBase = As_u + (uint32_t)(wm * 32 + (g & 1) * 8 + lr) * (ASTRIDE * 2)
                                + (uint32_t)((g >> 1) * 8) * 2;
    const uint32_t bBase = Bs_u + (uint32_t)(wn * 32 + (g >> 1) * 8 + lr) * (STRIDEB * 2)
                                + (uint32_t)((g & 1) * 8) * 2;

    {
        const float4* bsrc = (const float4*)Bimg;
        float4* bdst = (float4*)Bs;
        constexpr int NV = 128 * STRIDEB * 2 / 16;
        for (int i = tid; i < NV; i += 512) bdst[i] = bsrc[i];
    }

    const int lrow0 = tid >> 5;
    const int lk2   = (tid & 31) * 2;

    float2 v[8];
    auto load_chunk = [&](int m0, int c) {
        const float* src = (c < CHUNKS / 2) ? A1 : A2;
        int kb = (c & (CHUNKS / 2 - 1)) * 64;
#pragma unroll
        for (int i = 0; i < 8; i++) {
            int grow = min(m0 + lrow0 + 16 * i, n - 1);
            v[i] = *(const float2*)(src + (size_t)grow * ASTR32 + kb + lk2);
        }
    };

    int tile = blockIdx.x;
    if (tile < nTiles) load_chunk(tile * 128, 0);

    for (; tile < nTiles; tile += gridDim.x) {
        const int m0 = tile * 128;

        float acc[2][4][4];
#pragma unroll
        for (int a = 0; a < 2; a++)
#pragma unroll
            for (int b = 0; b < 4; b++)
#pragma unroll
                for (int q = 0; q < 4; q++) acc[a][b][q] = 0.0f;

        for (int c = 0; c < CHUNKS; ++c) {
            __syncthreads();

#pragma unroll
            for (int i = 0; i < 8; i++) {
                int row = lrow0 + 16 * i;
                __nv_bfloat16 h0 = __float2bfloat16_rn(v[i].x);
                __nv_bfloat16 h1 = __float2bfloat16_rn(v[i].y);
                __nv_bfloat16 l0 = __float2bfloat16_rn(v[i].x - __bfloat162float(h0));
                __nv_bfloat16 l1 = __float2bfloat16_rn(v[i].y - __bfloat162float(h1));
                uint32_t hp = ((uint32_t)__bfloat16_as_ushort(h1) << 16) | __bfloat16_as_ushort(h0);
                uint32_t lp = ((uint32_t)__bfloat16_as_ushort(l1) << 16) | __bfloat16_as_ushort(l0);
                *(uint32_t*)(As + row * ASTRIDE + lk2)      = hp;
                *(uint32_t*)(As + row * ASTRIDE + 64 + lk2) = lp;
            }

            {
                int nc = c + 1, nt = tile;
                if (nc == CHUNKS) { nc = 0; nt = tile + gridDim.x; }
                if (nt < nTiles) load_chunk(nt * 128, nc);
            }
            __syncthreads();

#pragma unroll
            for (int ks = 0; ks < 4; ks++) {
                uint32_t ah[2][4], al[2][4], bh[2][4], bl[2][4];
#pragma unroll
                for (int ma = 0; ma < 2; ma++) {
                    uint32_t a = aBase + (uint32_t)(ma * 16 * ASTRIDE * 2 + ks * 32);
                    ldsm_x4(ah[ma], a);
                    ldsm_x4(al[ma], a + 128);
                }
#pragma unroll
                for (int p = 0; p < 2; p++) {
                    uint32_t b = bBase + (uint32_t)(p * 16 * STRIDEB * 2 + c * 128 + ks * 32);
                    ldsm_x4(bh[p], b);
                    ldsm_x4(bl[p], b + KTOT * 2);
                }
#pragma unroll
                for (int pass = 0; pass < 3; pass++) {
                    const uint32_t (*Af)[4] = (pass == 1) ? al : ah;
                    const uint32_t (*Bf)[4] = (pass == 2) ? bl : bh;
#pragma unroll
                    for (int ma = 0; ma < 2; ma++)
#pragma unroll
                        for (int p = 0; p < 2; p++) {
                            mma16816(acc[ma][2 * p],     Af[ma], Bf[p][0], Bf[p][1]);
                            mma16816(acc[ma][2 * p + 1], Af[ma], Bf[p][2], Bf[p][3]);
                        }
                }
            }
        }

#pragma unroll
        for (int ma = 0; ma < 2; ma++) {
            int row = m0 + wm * 32 + ma * 16 + tq;
#pragma unroll
            for (int nb = 0; nb < 4; nb++) {
                int col = wn * 32 + nb * 8 + 2 * tr;
                float2 bv = *(const float2*)(bias + col);
                if (row < n) {
                    float2 o;
                    o.x = acc[ma][nb][0] + bv.x;
                    o.y = acc[ma][nb][1] + bv.y;
                    if (RELU) { o.x = fmaxf(o.x, 0.0f); o.y = fmaxf(o.y, 0.0f); }
                    *(float2*)(out + (size_t)row * 128 + col) = o;
                }
                if (row + 8 < n) {
                    float2 o;
                    o.x = acc[ma][nb][2] + bv.x;
                    o.y = acc[ma][nb][3] + bv.y;
                    if (RELU) { o.x = fmaxf(o.x, 0.0f); o.y = fmaxf(o.y, 0.0f); }
                    *(float2*)(out + (size_t)(row + 8) * 128 + col) = o;
                }
            }
        }
    }
}

// ---------------- global mean pool ----------------
__global__ void pool_acc_kernel(const float* __restrict__ h,
                                const int* __restrict__ batch,
                                float* __restrict__ out, int n, int G) {
    const int NPW = 16;
    int gw   = (blockIdx.x * blockDim.x + threadIdx.x) >> 5;
    int lane = threadIdx.x & 31;
    int beg = gw * NPW;
    if (beg >= n) return;
    int end = min(beg + NPW, n);
    float a0 = 0, a1 = 0, a2 = 0, a3 = 0;
    int cur = min(max(batch[beg], 0), G - 1);
    int cnt = 0;
    for (int i = beg; i < end; i++) {
        int b = min(max(batch[i], 0), G - 1);
        if (b != cur) {
            atomicAdd(&out[cur * 128 + lane +  0], a0);
            atomicAdd(&out[cur * 128 + lane + 32], a1);
            atomicAdd(&out[cur * 128 + lane + 64], a2);
            atomicAdd(&out[cur * 128 + lane + 96], a3);
            if (lane == 0) atomicAdd(&g_gcnt[cur], (float)cnt);
            a0 = a1 = a2 = a3 = 0.0f;
            cnt = 0;
            cur = b;
        }
        const float* row = h + (size_t)i * 128;
        a0 += row[lane];      a1 += row[lane + 32];
        a2 += row[lane + 64]; a3 += row[lane + 96];
        cnt++;
    }
    atomicAdd(&out[cur * 128 + lane +  0], a0);
    atomicAdd(&out[cur * 128 + lane + 32], a1);
    atomicAdd(&out[cur * 128 + lane + 64], a2);
    atomicAdd(&out[cur * 128 + lane + 96], a3);
    if (lane == 0) atomicAdd(&g_gcnt[cur], (float)cnt);
}

// final: divide by counts AND restore g_deg/g_cursor to zero for next call
__global__ void pool_div_kernel(float* out, int G, int n) {
    int i = blockIdx.x * blockDim.x + threadIdx.x;
    if (i < G * 128) out[i] /= fmaxf(g_gcnt[i >> 7], 1.0f);
    if (i < n) { g_deg[i] = 0; g_cursor[i] = 0; }
}

// ---------------- launch ----------------
extern "C" void kernel_launch(void* const* d_in, const int* in_sizes, int n_in,
                              void* d_out, int out_size) {
    const float* x     = (const float*)d_in[0];
    const int*   ei    = (const int*)d_in[1];
    const int*   batch = (const int*)d_in[2];
    const float* Wl1 = (const float*)d_in[3];
    const float* bl1 = (const float*)d_in[4];
    const float* Wr1 = (const float*)d_in[5];
    const float* Wl2 = (const float*)d_in[6];
    const float* bl2 = (const float*)d_in[7];
    const float* Wr2 = (const float*)d_in[8];
    const float* Wl3 = (const float*)d_in[9];
    const float* bl3 = (const float*)d_in[10];
    const float* Wr3 = (const float*)d_in[11];
    float* out = (float*)d_out;

    const int n = in_sizes[0] / 64;       // 50000
    const int E = in_sizes[1] / 2;        // 600000
    const int G = out_size / 128;         // 64

    const int* src = ei;
    const int* dst = ei + E;

    void *p_agg, *p_hA, *p_hB, *p_Bimg;
    cudaGetSymbolAddress(&p_agg, g_agg);
    cudaGetSymbolAddress(&p_hA, g_hA);
    cudaGetSymbolAddress(&p_hB, g_hB);
    cudaGetSymbolAddress(&p_Bimg, g_Bimg);
    float* agg = (float*)p_agg;
    float* hA  = (float*)p_hA;
    float* hB  = (float*)p_hB;
    unsigned short* Bimg = (unsigned short*)p_Bimg;

    const int smem1 = (128 * 136 + 128 * 264) * 2;   // 102400 (CHUNKS=2)
    const int smem2 = (128 * 136 + 128 * 520) * 2;   // 167936 (CHUNKS=4)
    cudaFuncSetAttribute(sage_mma<2, true >, cudaFuncAttributeMaxDynamicSharedMemorySize, smem1);
    cudaFuncSetAttribute(sage_mma<4, true >, cudaFuncAttributeMaxDynamicSharedMemorySize, smem2);
    cudaFuncSetAttribute(sage_mma<4, false>, cudaFuncAttributeMaxDynamicSharedMemorySize, smem2);

    const int aggBlocks = (n * 32 + 255) / 256;
    const int nTiles = (n + 127) / 128;
    const int gemmGrid = 148;
    int quads = (E + 3) / 4;

    // ---- CSR build first (g_deg/g_cursor zero by invariant) ----
    count_deg_kernel<<<(quads + 255) / 256, 256>>>(dst, E, n);       // 1
    scan_kernel<<<1, 1024>>>(n);                                      // 2
    scatter_kernel<<<(quads + 255) / 256, 256>>>(src, dst, E, n);     // 3

    // ---- agg layer 1 (launch #4 — ncu capture target) ----
    agg_kernel<64><<<aggBlocks, 256>>>(x, agg, n);                    // 4

    // ---- setup: zero out/gcnt + weight images ----
    {
        int total = G * 128 + G + 128 * 264 + 2 * (128 * 520);
        setup_kernel<<<(total + 255) / 256, 256>>>(Wl1, Wr1, Wl2, Wr2, Wl3, Wr3,
                                                   Bimg, out, G);     // 5
    }

    // ---- layer 1 GEMM ----
    sage_mma<2, true><<<gemmGrid, 512, smem1>>>(agg, x, Bimg, bl1, hA, n, nTiles);   // 6

    // ---- layer 2 ----
    agg_kernel<128><<<aggBlocks, 256>>>(hA, agg, n);                                  // 7
    sage_mma<4, true><<<gemmGrid, 512, smem2>>>(agg, hA, Bimg + 33792, bl2, hB, n, nTiles); // 8

    // ---- layer 3 ----
    agg_kernel<128><<<aggBlocks, 256>>>(hB, agg, n);                                  // 9
    sage_mma<4, false><<<gemmGrid, 512, smem2>>>(agg, hB, Bimg + 100352, bl3, hA, n, nTiles); // 10

    // ---- global mean pool + restore deg/cursor invariant ----
    int poolWarps = (n + 15) / 16;
    pool_acc_kernel<<<(poolWarps * 32 + 255) / 256, 256>>>(hA, batch, out, n, G);     // 11
    pool_div_kernel<<<(n + 255) / 256, 256>>>(out, G, n);                             // 12
}